// round 11
// baseline (speedup 1.0000x reference)
#include <cuda_runtime.h>
#include <cstdint>

#define SEQ    512
#define BATCH  1024
#define INF    256
#define HID    512
#define OUTF   64
#define NB     8
#define BK     8
#define NIT    (INF / BK)        // 32
#define NTILES (SEQ * 64)        // per t: 8 bm-tiles x 8 bn-tiles (128x64 tiles)
#define NBLK   148

// ---------------- scratch (static device allocations; no cudaMalloc) --------
__device__ float g_cur[(size_t)SEQ * BATCH * HID];   // X @ w_in.T for all t
__device__ float g_winT[INF * HID];                  // w_in  transposed [k][h]
__device__ float g_wrecT[HID * HID];                 // w_rec transposed [h'][h]
__device__ float g_woutT[HID * OUTF];                // w_out transposed [h][o]
__device__ int   g_flag[SEQ * 8];                    // per (t, bm) done count (target 8)
__device__ int   g_tilectr;                          // producer work counter

// ---------------- setup: transposes + flag reset -----------------------------
__global__ void setup_kernel(const float* __restrict__ w_in,
                             const float* __restrict__ w_rec,
                             const float* __restrict__ w_out) {
    int stride = gridDim.x * blockDim.x;
    int idx = blockIdx.x * blockDim.x + threadIdx.x;
    for (int i = idx; i < INF * HID; i += stride) {
        int k = i / HID, h = i % HID;
        g_winT[i] = w_in[h * INF + k];
    }
    for (int i = idx; i < HID * HID; i += stride) {
        int hp = i / HID, h = i % HID;
        g_wrecT[i] = w_rec[h * HID + hp];
    }
    for (int i = idx; i < HID * OUTF; i += stride) {
        int h = i / OUTF, o = i % OUTF;
        g_woutT[i] = w_out[o * HID + h];
    }
    for (int i = idx; i < SEQ * 8; i += stride) g_flag[i] = 0;
    if (idx == 0) g_tilectr = 0;
}

// ---------------- helpers ------------------------------------------------------
__device__ __forceinline__ unsigned long long dup_f32x2(float x) {
    unsigned long long d;
    asm("mov.b64 %0, {%1, %1};" : "=l"(d) : "f"(x));
    return d;
}
__device__ __forceinline__ void ffma2(unsigned long long& acc,
                                      unsigned long long a,
                                      unsigned long long b) {
    asm("fma.rn.f32x2 %0, %1, %2, %0;" : "+l"(acc) : "l"(a), "l"(b));
}
__device__ __forceinline__ void barsync(int id, int cnt) {
    asm volatile("bar.sync %0, %1;" :: "r"(id), "r"(cnt) : "memory");
}

// ---------------- producer team: 512 threads, 128x64 GEMM tiles ---------------
// fp32, strictly k-ascending single-accumulator FMA chains, FFMA2 (per-lane
// IEEE fp32). Region layout: Xs 2x8x128 f32 (8192 B), Ws 2x8x64 f32 (4096 B),
// tile counter int. Tiles in ascending-t order via global atomic.
__device__ void producer_team(const float* __restrict__ X, char* base, int t,
                              int barid) {
    float (*Xs)[BK][128] = reinterpret_cast<float (*)[BK][128]>(base);
    float (*Ws)[BK][64]  = reinterpret_cast<float (*)[BK][64]>(base + 8192);
    int* s_tile = reinterpret_cast<int*>(base + 12288);

    const int ty = t >> 3;                // 0..63 : rows 2ty, 2ty+1
    const int tx = t & 7;                 // 0..7  : cols tx*8 .. tx*8+7
    const int xm = t >> 2;                // 0..127: X-load row
    const int xj = (t & 3) * 2;           // 0,2,4,6: X-load k pair
    const int wk = t >> 6;                // 0..7  : W-load k row
    const int wn = t & 63;                // 0..63 : W-load col

    for (;;) {
        if (t == 0) *s_tile = atomicAdd(&g_tilectr, 1);
        barsync(barid, 512);
        const int T = *s_tile;
        if (T >= NTILES) return;

        const int tt  = T >> 6;
        const int rem = T & 63;
        const int bm  = rem >> 3;         // 0..7 within t
        const int bn  = rem & 7;          // 0..7
        const int bmg = tt * 8 + bm;

        const float* Xblk = X + (size_t)bmg * 128 * INF;
        const float* Wblk = g_winT + bn * 64;

        unsigned long long acc2[2][4];
#pragma unroll
        for (int i = 0; i < 2; i++)
#pragma unroll
            for (int j = 0; j < 4; j++) acc2[i][j] = 0ull;

        // preload iter 0
        float2 xv = *(const float2*)(Xblk + (size_t)xm * INF + xj);
        float  wv = Wblk[(size_t)wk * HID + wn];
        Xs[0][xj][xm]     = xv.x;
        Xs[0][xj + 1][xm] = xv.y;
        Ws[0][wk][wn]     = wv;
        barsync(barid, 512);

        for (int it = 0; it < NIT; it++) {
            const int cur = it & 1;
            const int nxt = cur ^ 1;
            const int k0n = (it + 1) * BK;
            if (it + 1 < NIT) {
                xv = *(const float2*)(Xblk + (size_t)xm * INF + k0n + xj);
                wv = Wblk[(size_t)(k0n + wk) * HID + wn];
            }
#pragma unroll
            for (int kk = 0; kk < BK; kk++) {
                unsigned long long a0 = dup_f32x2(Xs[cur][kk][2 * ty]);
                unsigned long long a1 = dup_f32x2(Xs[cur][kk][2 * ty + 1]);
                ulonglong2 b01 = *(const ulonglong2*)&Ws[cur][kk][tx * 8];
                ulonglong2 b23 = *(const ulonglong2*)&Ws[cur][kk][tx * 8 + 4];
                ffma2(acc2[0][0], a0, b01.x);
                ffma2(acc2[0][1], a0, b01.y);
                ffma2(acc2[0][2], a0, b23.x);
                ffma2(acc2[0][3], a0, b23.y);
                ffma2(acc2[1][0], a1, b01.x);
                ffma2(acc2[1][1], a1, b01.y);
                ffma2(acc2[1][2], a1, b23.x);
                ffma2(acc2[1][3], a1, b23.y);
            }
            if (it + 1 < NIT) {
                Xs[nxt][xj][xm]     = xv.x;
                Xs[nxt][xj + 1][xm] = xv.y;
                Ws[nxt][wk][wn]     = wv;
            }
            barsync(barid, 512);
        }

        float* Cblk = g_cur + (size_t)bmg * 128 * HID + bn * 64;
#pragma unroll
        for (int i = 0; i < 2; i++) {
            *(float4*)(Cblk + (size_t)(2 * ty + i) * HID + tx * 8)     = *(float4*)&acc2[i][0];
            *(float4*)(Cblk + (size_t)(2 * ty + i) * HID + tx * 8 + 4) = *(float4*)&acc2[i][2];
        }

        __threadfence();          // order this thread's STGs before the flag
        barsync(barid, 512);
        if (t == 0) atomicAdd(&g_flag[tt * 8 + bm], 1);
    }
}

// ---------------- scanner: 512 threads, NB=8 batch rows (R7-exact) -----------
// Per-(row,h) op sequence bitwise-identical to the R7/R8 passing kernels.
// Uses named barrier 1 (512 participants) so producer warps never block.
__device__ void scanner_body(float* __restrict__ out, char* sraw, int sb, int tid) {
    int (*s_list)[NB][HID] = reinterpret_cast<int (*)[NB][HID]>(sraw);
    int (*s_cnt)[NB]       = reinterpret_cast<int (*)[NB]>(sraw + 32768);
    int (*s_wcnt)[16]      = reinterpret_cast<int (*)[16]>(sraw + 32832);

    const int h    = tid;
    const int lane = tid & 31;
    const int warp = tid >> 5;           // 0..15
    const int row0 = sb * NB;
    const int prow = tid >> 6;           // 0..7
    const int po   = tid & 63;           // 0..63
    const int fidx = sb >> 4;            // bm tile covering rows of this block

    float v[NB], isyn[NB];
#pragma unroll
    for (int r = 0; r < NB; r++) { v[r] = 0.0f; isyn[r] = 0.0f; }
    float vo = 0.0f, io = 0.0f;

    if (tid < 2 * NB) ((int*)s_cnt)[tid] = 0;
    barsync(1, 512);

    for (int t = 0; t < SEQ; t++) {
        const int oldp = t & 1;
        const int newp = oldp ^ 1;

        // wait until producers finished this step's tiles (8 bn-tiles)
        if (tid == 0) {
            volatile int* f = &g_flag[t * 8 + fidx];
            while (*f < 8) __nanosleep(64);
            __threadfence();
        }
        barsync(1, 512);

        float zn[NB], ipart[NB];
#pragma unroll
        for (int r = 0; r < NB; r++) {
            float c  = g_cur[((size_t)t * BATCH + row0 + r) * HID + h];
            // t1 = (0 - v) + i   (two separately-rounded ops)
            float t1 = __fadd_rn(__fsub_rn(0.0f, v[r]), isyn[r]);
            // v_dec = v + 0.1*t1  -> contracted FFMA
            float vd = fmaf(0.1f, t1, v[r]);
            // i_dec = i + 0.2*(-i) -> contracted FFMA
            float id = fmaf(0.2f, -isyn[r], isyn[r]);
            // z = (v_dec - 1 > 0)
            float z  = (__fsub_rn(vd, 1.0f) > 0.0f) ? 1.0f : 0.0f;
            zn[r] = z;
            // v_new = (1-z)*v_dec + z*0
            v[r] = __fadd_rn(__fmul_rn(__fsub_rn(1.0f, z), vd), __fmul_rn(z, 0.0f));
            // (i_dec + g1)
            ipart[r] = __fadd_rn(id, c);
        }

        // build new spike lists (ascending h)
        unsigned masks[NB];
#pragma unroll
        for (int r = 0; r < NB; r++) {
            masks[r] = __ballot_sync(0xffffffffu, zn[r] != 0.0f);
            if (lane == 0) s_wcnt[r][warp] = __popc(masks[r]);
        }
        barsync(1, 512);   // sync1: warp counts visible
#pragma unroll
        for (int r = 0; r < NB; r++) {
            int base = 0;
#pragma unroll
            for (int w = 0; w < 16; w++) base += (w < warp) ? s_wcnt[r][w] : 0;
            if (zn[r] != 0.0f) {
                int pos = base + __popc(masks[r] & ((1u << lane) - 1u));
                s_list[newp][r][pos] = h;
            }
        }
        if (tid < NB) {
            int tot = 0;
#pragma unroll
            for (int w = 0; w < 16; w++) tot += s_wcnt[tid][w];
            s_cnt[newp][tid] = tot;
        }

        // recurrent gather with OLD spike list (list-ascending accumulation)
#pragma unroll
        for (int r = 0; r < NB; r++) {
            float racc = 0.0f;
            const int n = s_cnt[oldp][r];
            const int* lst = s_list[oldp][r];
            int s = 0;
            for (; s + 4 <= n; s += 4) {
                int a0 = lst[s], a1 = lst[s + 1], a2 = lst[s + 2], a3 = lst[s + 3];
                float w0 = g_wrecT[a0 * HID + h];
                float w1 = g_wrecT[a1 * HID + h];
                float w2 = g_wrecT[a2 * HID + h];
                float w3 = g_wrecT[a3 * HID + h];
                racc = __fadd_rn(racc, w0);
                racc = __fadd_rn(racc, w1);
                racc = __fadd_rn(racc, w2);
                racc = __fadd_rn(racc, w3);
            }
            for (; s < n; s++) racc = __fadd_rn(racc, g_wrecT[lst[s] * HID + h]);
            // i_new = (i_dec + g1) + g2
            isyn[r] = __fadd_rn(ipart[r], racc);
        }

        barsync(1, 512);   // sync2: new lists + counts complete

        // readout gather with NEW spike list + LI cell
        {
            float y = 0.0f;
            const int n = s_cnt[newp][prow];
            const int* lst = s_list[newp][prow];
            int s = 0;
            for (; s + 4 <= n; s += 4) {
                int a0 = lst[s], a1 = lst[s + 1], a2 = lst[s + 2], a3 = lst[s + 3];
                float w0 = g_woutT[a0 * OUTF + po];
                float w1 = g_woutT[a1 * OUTF + po];
                float w2 = g_woutT[a2 * OUTF + po];
                float w3 = g_woutT[a3 * OUTF + po];
                y = __fadd_rn(y, w0);
                y = __fadd_rn(y, w1);
                y = __fadd_rn(y, w2);
                y = __fadd_rn(y, w3);
            }
            for (; s < n; s++) y = __fadd_rn(y, g_woutT[lst[s] * OUTF + po]);

            // t1o = (0 - vo) + io ; vo_new = vo + 0.1*t1o -> contracted FFMA
            float t1o = __fadd_rn(__fsub_rn(0.0f, vo), io);
            float von = fmaf(0.1f, t1o, vo);
            // io_dec = io + 0.2*(-io) -> contracted FFMA
            float iod = fmaf(0.2f, -io, io);
            vo = von;
            io = __fadd_rn(iod, y);

            out[((size_t)t * BATCH + row0 + prow) * OUTF + po] = vo;
        }
    }
}

// ---------------- fused kernel: mixed-role blocks ------------------------------
// Blocks 0..127: warps 0-15 scan 8 batch rows; warps 16-31 are a GEMM team.
// Blocks 128..147: two GEMM teams. 1 block/SM, all 148 blocks resident.
__global__ __launch_bounds__(1024, 1) void fused_kernel(const float* __restrict__ X,
                                                        float* __restrict__ out) {
    __shared__ __align__(16) char sraw[45664];
    const int tid = threadIdx.x;
    const int b   = blockIdx.x;
    if (b < 128) {
        if (tid < 512) scanner_body(out, sraw, b, tid);
        else           producer_team(X, sraw + 33344, tid - 512, 2);
    } else {
        if (tid < 512) producer_team(X, sraw, tid, 1);
        else           producer_team(X, sraw + 16384, tid - 512, 2);
    }
}

// ---------------- launch -----------------------------------------------------
extern "C" void kernel_launch(void* const* d_in, const int* in_sizes, int n_in,
                              void* d_out, int out_size) {
    const float* x     = (const float*)d_in[0];   // [512,1024,256]
    const float* w_in  = (const float*)d_in[1];   // [512,256]
    const float* w_rec = (const float*)d_in[2];   // [512,512]
    const float* w_out = (const float*)d_in[3];   // [64,512]
    float* out = (float*)d_out;                   // [512,1024,64]

    setup_kernel<<<128, 256>>>(w_in, w_rec, w_out);
    fused_kernel<<<NBLK, 1024>>>(x, out);
}

// round 12
// speedup vs baseline: 1.6603x; 1.6603x over previous
#include <cuda_runtime.h>
#include <cstdint>

#define SEQ    512
#define BATCH  1024
#define INF    256
#define HID    512
#define OUTF   64
#define NB     8            // batch rows per scanner block
#define NPROD  168          // producer blocks
#define NSCAN  128          // scanner blocks = BATCH/NB
#define NTILES (SEQ * 32)   // per t: 8 bm-tiles x 4 bn-tiles

#define BM 128
#define BN 128
#define BK 8

// ---------------- scratch (static device allocations; no cudaMalloc) --------
__device__ float g_cur[(size_t)SEQ * BATCH * HID];   // X @ w_in.T for all t
__device__ float g_winT[INF * HID];                  // w_in  transposed [k][h]
__device__ float g_wrecT[HID * HID];                 // w_rec transposed [h'][h]
__device__ float g_woutT[HID * OUTF];                // w_out transposed [h][o]
__device__ int   g_flag[SEQ * 8];                    // per (t, bm-within-t) done count (target 4)
__device__ int   g_tilectr;                          // producer work counter

// ---------------- setup: transposes + flag reset -----------------------------
__global__ void setup_kernel(const float* __restrict__ w_in,
                             const float* __restrict__ w_rec,
                             const float* __restrict__ w_out) {
    int stride = gridDim.x * blockDim.x;
    int idx = blockIdx.x * blockDim.x + threadIdx.x;
    for (int i = idx; i < INF * HID; i += stride) {
        int k = i / HID, h = i % HID;
        g_winT[i] = w_in[h * INF + k];
    }
    for (int i = idx; i < HID * HID; i += stride) {
        int hp = i / HID, h = i % HID;
        g_wrecT[i] = w_rec[h * HID + hp];
    }
    for (int i = idx; i < HID * OUTF; i += stride) {
        int h = i / OUTF, o = i % OUTF;
        g_woutT[i] = w_out[o * HID + h];
    }
    for (int i = idx; i < SEQ * 8; i += stride) g_flag[i] = 0;
    if (idx == 0) g_tilectr = 0;
}

// ---------------- FFMA2 helpers ----------------------------------------------
__device__ __forceinline__ unsigned long long dup_f32x2(float x) {
    unsigned long long d;
    asm("mov.b64 %0, {%1, %1};" : "=l"(d) : "f"(x));
    return d;
}
__device__ __forceinline__ void ffma2(unsigned long long& acc,
                                      unsigned long long a,
                                      unsigned long long b) {
    asm("fma.rn.f32x2 %0, %1, %2, %0;" : "+l"(acc) : "l"(a), "l"(b));
}

// ---------------- producer role (identical to R10's, proven bitwise) ---------
__device__ void producer_body(const float* __restrict__ X, char* sraw, int tid) {
    float (*Xs)[BK][BM] = reinterpret_cast<float (*)[BK][BM]>(sraw);
    float (*Ws)[BK][BN] = reinterpret_cast<float (*)[BK][BN]>(sraw + 8192);
    int* s_tile = reinterpret_cast<int*>(sraw + 16384);

    const int tx = tid % 16;
    const int ty = tid / 16;
    const int lm = tid >> 1;              // 0..127
    const int lk = (tid & 1) * 4;         // 0 or 4
    const int wk = tid >> 5;              // 0..7
    const int wn = (tid & 31) * 4;        // 0..124
    const int NIT = INF / BK;             // 32

    for (;;) {
        if (tid == 0) *s_tile = atomicAdd(&g_tilectr, 1);
        __syncthreads();
        const int T = *s_tile;
        if (T >= NTILES) return;

        const int t   = T >> 5;
        const int rem = T & 31;
        const int bml = rem >> 2;
        const int bn  = rem & 3;
        const int bm  = t * 8 + bml;

        const float* Xblk = X + (size_t)bm * BM * INF;
        const float* Wblk = g_winT + bn * BN;

        unsigned long long acc2[8][4];
#pragma unroll
        for (int i = 0; i < 8; i++)
#pragma unroll
            for (int j = 0; j < 4; j++) acc2[i][j] = 0ull;

        float4 xv = *(const float4*)(Xblk + (size_t)lm * INF + 0 + lk);
        float4 wv = *(const float4*)(Wblk + (size_t)(0 + wk) * HID + wn);
        Xs[0][lk + 0][lm] = xv.x;
        Xs[0][lk + 1][lm] = xv.y;
        Xs[0][lk + 2][lm] = xv.z;
        Xs[0][lk + 3][lm] = xv.w;
        *(float4*)&Ws[0][wk][wn] = wv;
        __syncthreads();

        for (int it = 0; it < NIT; it++) {
            const int cur = it & 1;
            const int nxt = cur ^ 1;
            const int k0n = (it + 1) * BK;
            if (it + 1 < NIT) {
                xv = *(const float4*)(Xblk + (size_t)lm * INF + k0n + lk);
                wv = *(const float4*)(Wblk + (size_t)(k0n + wk) * HID + wn);
            }
#pragma unroll
            for (int kk = 0; kk < BK; kk++) {
                float4 xa = *(const float4*)&Xs[cur][kk][ty * 8];
                float4 xb = *(const float4*)&Xs[cur][kk][ty * 8 + 4];
                unsigned long long a2[8];
                a2[0] = dup_f32x2(xa.x); a2[1] = dup_f32x2(xa.y);
                a2[2] = dup_f32x2(xa.z); a2[3] = dup_f32x2(xa.w);
                a2[4] = dup_f32x2(xb.x); a2[5] = dup_f32x2(xb.y);
                a2[6] = dup_f32x2(xb.z); a2[7] = dup_f32x2(xb.w);
                ulonglong2 b01 = *(const ulonglong2*)&Ws[cur][kk][tx * 8];
                ulonglong2 b23 = *(const ulonglong2*)&Ws[cur][kk][tx * 8 + 4];
                unsigned long long b2[4] = {b01.x, b01.y, b23.x, b23.y};
#pragma unroll
                for (int i = 0; i < 8; i++)
#pragma unroll
                    for (int j = 0; j < 4; j++)
                        ffma2(acc2[i][j], a2[i], b2[j]);
            }
            if (it + 1 < NIT) {
                Xs[nxt][lk + 0][lm] = xv.x;
                Xs[nxt][lk + 1][lm] = xv.y;
                Xs[nxt][lk + 2][lm] = xv.z;
                Xs[nxt][lk + 3][lm] = xv.w;
                *(float4*)&Ws[nxt][wk][wn] = wv;
            }
            __syncthreads();
        }

        float* Cblk = g_cur + (size_t)bm * BM * HID + bn * BN;
#pragma unroll
        for (int i = 0; i < 8; i++) {
            *(float4*)(Cblk + (size_t)(ty * 8 + i) * HID + tx * 8)     = *(float4*)&acc2[i][0];
            *(float4*)(Cblk + (size_t)(ty * 8 + i) * HID + tx * 8 + 4) = *(float4*)&acc2[i][2];
        }

        __threadfence();
        __syncthreads();
        if (tid == 0) atomicAdd(&g_flag[t * 8 + bml], 1);
    }
}

// ---------------- scanner role: 256 threads, NB=8 rows, float2 h-pairs -------
// Thread owns h0=2*tid, h1=2*tid+1. All weight/current accesses are float2.
// Per-(row,h) arithmetic sequence and list-ascending accumulation identical to
// the bitwise-verified R7/R8/R10 kernels.
__device__ void scanner_body(float* __restrict__ out, char* sraw, int sb, int tid) {
    int (*s_list)[NB][HID] = reinterpret_cast<int (*)[NB][HID]>(sraw);
    int (*s_cnt)[NB]       = reinterpret_cast<int (*)[NB]>(sraw + 32768);
    int (*s_wcnt)[8]       = reinterpret_cast<int (*)[8]>(sraw + 32832);

    const int lane = tid & 31;
    const int warp = tid >> 5;           // 0..7 ; warp covers h in [64w, 64w+63]
    const int row0 = sb * NB;
    const int prow = warp;               // readout row 0..7
    const int fidx = sb >> 4;            // bm tile covering this block's rows
    const unsigned below = (1u << lane) - 1u;

    float v[NB][2], isyn[NB][2];
#pragma unroll
    for (int r = 0; r < NB; r++)
#pragma unroll
        for (int k = 0; k < 2; k++) { v[r][k] = 0.0f; isyn[r][k] = 0.0f; }
    float vo[2] = {0.0f, 0.0f}, io[2] = {0.0f, 0.0f};

    if (tid < 2 * NB) ((int*)s_cnt)[tid] = 0;
    __syncthreads();

    unsigned m0[NB], m1[NB];

    for (int t = 0; t < SEQ; t++) {
        const int oldp = t & 1;
        const int newp = oldp ^ 1;

        // acquire this step's g_cur tiles (each thread independently)
        {
            volatile int* f = &g_flag[t * 8 + fidx];
            while (*f < 4) __nanosleep(64);
            __threadfence();
        }

#pragma unroll
        for (int r = 0; r < NB; r++) {
            float2 c = *(const float2*)&g_cur[((size_t)t * BATCH + row0 + r) * HID + 2 * tid];
            float cc[2] = {c.x, c.y};
            float zz[2];
#pragma unroll
            for (int hi = 0; hi < 2; hi++) {
                // t1 = (0 - v) + i   (two separately-rounded ops)
                float t1 = __fadd_rn(__fsub_rn(0.0f, v[r][hi]), isyn[r][hi]);
                // v_dec = v + 0.1*t1  -> contracted FFMA
                float vd = fmaf(0.1f, t1, v[r][hi]);
                // i_dec = i + 0.2*(-i) -> contracted FFMA
                float id = fmaf(0.2f, -isyn[r][hi], isyn[r][hi]);
                // z = (v_dec - 1 > 0)
                float z  = (__fsub_rn(vd, 1.0f) > 0.0f) ? 1.0f : 0.0f;
                zz[hi] = z;
                // v_new = (1-z)*v_dec + z*0
                v[r][hi] = __fadd_rn(__fmul_rn(__fsub_rn(1.0f, z), vd), __fmul_rn(z, 0.0f));
                // ipart = i_dec + g1 (held in isyn until gather adds g2)
                isyn[r][hi] = __fadd_rn(id, cc[hi]);
            }
            m0[r] = __ballot_sync(0xffffffffu, zz[0] != 0.0f);
            m1[r] = __ballot_sync(0xffffffffu, zz[1] != 0.0f);
            if (lane == 0) s_wcnt[r][warp] = __popc(m0[r]) + __popc(m1[r]);
        }
        __syncthreads();   // sync1: warp counts visible

        // insert spikes in ascending-h order: within warp, h = 64w + 2l (+1)
#pragma unroll
        for (int r = 0; r < NB; r++) {
            int base = 0;
#pragma unroll
            for (int w = 0; w < 8; w++) base += (w < warp) ? s_wcnt[r][w] : 0;
            int pos = base + __popc(m0[r] & below) + __popc(m1[r] & below);
            const int b0 = (m0[r] >> lane) & 1;
            if (b0)                  s_list[newp][r][pos]      = 2 * tid;
            if ((m1[r] >> lane) & 1) s_list[newp][r][pos + b0] = 2 * tid + 1;
        }
        if (tid < NB) {
            int tot = 0;
#pragma unroll
            for (int w = 0; w < 8; w++) tot += s_wcnt[tid][w];
            s_cnt[newp][tid] = tot;
        }

        // recurrent gather with OLD spike list (float2: both h of this thread)
#pragma unroll
        for (int r = 0; r < NB; r++) {
            float r0 = 0.0f, r1 = 0.0f;
            const int n = s_cnt[oldp][r];
            const int* lst = s_list[oldp][r];
            int s = 0;
            for (; s + 4 <= n; s += 4) {
                int a0 = lst[s], a1 = lst[s + 1], a2 = lst[s + 2], a3 = lst[s + 3];
                float2 w0 = *(const float2*)&g_wrecT[a0 * HID + 2 * tid];
                float2 w1 = *(const float2*)&g_wrecT[a1 * HID + 2 * tid];
                float2 w2 = *(const float2*)&g_wrecT[a2 * HID + 2 * tid];
                float2 w3 = *(const float2*)&g_wrecT[a3 * HID + 2 * tid];
                r0 = __fadd_rn(r0, w0.x);
                r0 = __fadd_rn(r0, w1.x);
                r0 = __fadd_rn(r0, w2.x);
                r0 = __fadd_rn(r0, w3.x);
                r1 = __fadd_rn(r1, w0.y);
                r1 = __fadd_rn(r1, w1.y);
                r1 = __fadd_rn(r1, w2.y);
                r1 = __fadd_rn(r1, w3.y);
            }
            for (; s < n; s++) {
                float2 w = *(const float2*)&g_wrecT[lst[s] * HID + 2 * tid];
                r0 = __fadd_rn(r0, w.x);
                r1 = __fadd_rn(r1, w.y);
            }
            // i_new = (i_dec + g1) + g2
            isyn[r][0] = __fadd_rn(isyn[r][0], r0);
            isyn[r][1] = __fadd_rn(isyn[r][1], r1);
        }

        __syncthreads();   // sync2: new lists + counts complete

        // readout gather with NEW spike list + LI cell (cols 2*lane, 2*lane+1)
        {
            float y0 = 0.0f, y1 = 0.0f;
            const int n = s_cnt[newp][prow];
            const int* lst = s_list[newp][prow];
            int s = 0;
            for (; s + 4 <= n; s += 4) {
                int a0 = lst[s], a1 = lst[s + 1], a2 = lst[s + 2], a3 = lst[s + 3];
                float2 u0 = *(const float2*)&g_woutT[a0 * OUTF + 2 * lane];
                float2 u1 = *(const float2*)&g_woutT[a1 * OUTF + 2 * lane];
                float2 u2 = *(const float2*)&g_woutT[a2 * OUTF + 2 * lane];
                float2 u3 = *(const float2*)&g_woutT[a3 * OUTF + 2 * lane];
                y0 = __fadd_rn(y0, u0.x);
                y0 = __fadd_rn(y0, u1.x);
                y0 = __fadd_rn(y0, u2.x);
                y0 = __fadd_rn(y0, u3.x);
                y1 = __fadd_rn(y1, u0.y);
                y1 = __fadd_rn(y1, u1.y);
                y1 = __fadd_rn(y1, u2.y);
                y1 = __fadd_rn(y1, u3.y);
            }
            for (; s < n; s++) {
                float2 u = *(const float2*)&g_woutT[lst[s] * OUTF + 2 * lane];
                y0 = __fadd_rn(y0, u.x);
                y1 = __fadd_rn(y1, u.y);
            }
            float yy[2] = {y0, y1};
            float von[2];
#pragma unroll
            for (int k = 0; k < 2; k++) {
                // t1o = (0 - vo) + io ; vo_new = vo + 0.1*t1o -> contracted FFMA
                float t1o = __fadd_rn(__fsub_rn(0.0f, vo[k]), io[k]);
                von[k] = fmaf(0.1f, t1o, vo[k]);
                // io_dec = io + 0.2*(-io) -> contracted FFMA
                float iod = fmaf(0.2f, -io[k], io[k]);
                vo[k] = von[k];
                io[k] = __fadd_rn(iod, yy[k]);
            }
            *(float2*)&out[((size_t)t * BATCH + row0 + prow) * OUTF + 2 * lane] =
                make_float2(von[0], von[1]);
        }
    }
}

// ---------------- fused kernel -----------------------------------------------
__global__ __launch_bounds__(256, 2) void fused_kernel(const float* __restrict__ X,
                                                       float* __restrict__ out) {
    __shared__ __align__(16) char sraw[33352];
    if (blockIdx.x < NPROD) {
        producer_body(X, sraw, threadIdx.x);
    } else {
        scanner_body(out, sraw, blockIdx.x - NPROD, threadIdx.x);
    }
}

// ---------------- launch -----------------------------------------------------
extern "C" void kernel_launch(void* const* d_in, const int* in_sizes, int n_in,
                              void* d_out, int out_size) {
    const float* x     = (const float*)d_in[0];   // [512,1024,256]
    const float* w_in  = (const float*)d_in[1];   // [512,256]
    const float* w_rec = (const float*)d_in[2];   // [512,512]
    const float* w_out = (const float*)d_in[3];   // [64,512]
    float* out = (float*)d_out;                   // [512,1024,64]

    setup_kernel<<<128, 256>>>(w_in, w_rec, w_out);
    fused_kernel<<<NPROD + NSCAN, 256>>>(x, out);
}